// round 17
// baseline (speedup 1.0000x reference)
#include <cuda_runtime.h>
#include <math.h>
#include <stdint.h>

// Problem constants
#define BB   4
#define SS   2048
#define DD   1024
#define HH   16
#define DHH  64
#define MM   (BB * SS)          // 8192 rows
#define MASKV (-1000000.0f)

// Scratch (device globals: allocation-free rule)
// Q/K/V hold tf32 BITS in flash-ready layouts (written by gemm epilogue).
__device__ unsigned g_Qh[(size_t)MM * DD];
__device__ unsigned g_Kh[(size_t)MM * DD];
__device__ unsigned g_Vh[(size_t)MM * DD];
__device__ float    g_Oc[(size_t)MM * DD];  // [B,S,D] concat-head attn output
__device__ unsigned g_Wt[(size_t)4 * DD * DD];  // tf32 quad-layout Wq,Wk,Wv,Wo

// ---------------------------------------------------------------------------
// Helpers
// ---------------------------------------------------------------------------
__device__ __forceinline__ uint32_t smem_u32(const void* p) {
    uint32_t a;
    asm("{ .reg .u64 t; cvta.to.shared.u64 t, %1; cvt.u32.u64 %0, t; }" : "=r"(a) : "l"(p));
    return a;
}
__device__ __forceinline__ unsigned f2tf(float x) {
    unsigned u;
    asm("cvt.rna.tf32.f32 %0, %1;" : "=r"(u) : "f"(x));
    return u;
}
__device__ __forceinline__ void mma8(float* d, const unsigned* a, const unsigned* b) {
    asm volatile(
        "mma.sync.aligned.m16n8k8.row.col.f32.tf32.tf32.f32 "
        "{%0,%1,%2,%3}, {%4,%5,%6,%7}, {%8,%9}, {%0,%1,%2,%3};"
        : "+f"(d[0]), "+f"(d[1]), "+f"(d[2]), "+f"(d[3])
        : "r"(a[0]), "r"(a[1]), "r"(a[2]), "r"(a[3]), "r"(b[0]), "r"(b[1]));
}
__device__ __forceinline__ void cpa16(uint32_t dst, const void* src) {
    asm volatile("cp.async.cg.shared.global [%0], [%1], 16;" :: "r"(dst), "l"(src));
}
#define CPA_COMMIT() asm volatile("cp.async.commit_group;" ::: "memory")
#define CPA_WAIT1()  asm volatile("cp.async.wait_group 1;" ::: "memory")
#define CPA_WAIT0()  asm volatile("cp.async.wait_group 0;" ::: "memory")

// ---------------------------------------------------------------------------
// QKV destination layouts (per head matrix = 2048 x 64 = 131072 words).
//   z=0 (Q): per 128-row qt-block, per warp w, quad layout:
//     word = head*131072 + qt*8192 + ((w*8+kc)*32 + g*4 + t)*4 + sel*2 + hi
//     where s = 128qt + 16w + 8sel + g, dh = 8kc + 4hi + t.
//   z=1 (K): per 64-row block kbi, quad layout over nj pairs p:
//     word = head*131072 + kbi*4096 + ((p*8+kc)*32 + g*4 + t)*4 + sel*2 + hi
//     where r = s%64 = 16p + 8sel + g.
//   z=2 (V): per 64-row block, pair layout:
//     word = head*131072 + kbi*4096 + (q*64 + dh)*2 + which
//     where r = 8*(q>>2) + (q&3) + 4*which.
// ---------------------------------------------------------------------------
__device__ __forceinline__ size_t qkv_addr(int z, int head, int s_, int dh) {
    if (z == 0) {
        int qt = s_ >> 7, w = (s_ >> 4) & 7, gg = s_ & 7, sel = (s_ >> 3) & 1;
        int kc = dh >> 3, hi = (dh >> 2) & 1, tt = dh & 3;
        return (size_t)head * 131072 + qt * 8192
             + (size_t)(((w * 8 + kc) * 32 + gg * 4 + tt) * 4 + sel * 2 + hi);
    } else if (z == 1) {
        int kbi = s_ >> 6, r = s_ & 63;
        int p = r >> 4, sel = (r >> 3) & 1, gg = r & 7;
        int kc = dh >> 3, hi = (dh >> 2) & 1, tt = dh & 3;
        return (size_t)head * 131072 + kbi * 4096
             + (size_t)(((p * 8 + kc) * 32 + gg * 4 + tt) * 4 + sel * 2 + hi);
    } else {
        int kbi = s_ >> 6, r = s_ & 63;
        int q = ((r >> 3) << 2) + (r & 3), which = (r >> 2) & 1;
        return (size_t)head * 131072 + kbi * 4096 + (size_t)((q * 64 + dh) * 2 + which);
    }
}

// ---------------------------------------------------------------------------
// Weight pre-convert + QUAD re-layout (fp32 -> tf32 bits), once per run.
// word = (p*128 + kc)*128 + (g*4 + t)*4 + sel*2 + hi  (n = 16p+8sel+g, k = 8kc+4hi+t)
// ---------------------------------------------------------------------------
struct CArgs { const float* W[4]; };

__global__ __launch_bounds__(256) void cvt_w(CArgs a, unsigned* __restrict__ out)
{
    const int w = blockIdx.y;
    const int i = blockIdx.x * 256 + threadIdx.x;       // 0..262143 float4s
    const int n  = i >> 8;
    const int k0 = (i << 2) & 1023;
    float4 v = ((const float4*)a.W[w])[i];

    const int p   = n >> 4;
    const int g   = n & 7;
    const int sel = (n >> 3) & 1;
    const int kc  = k0 >> 3;
    const int hi  = (k0 >> 2) & 1;
    unsigned* ob = out + (size_t)w * DD * DD
                 + ((size_t)(p * 128 + kc) * 32 + g * 4) * 4 + (sel * 2 + hi);
    ob[0]  = f2tf(v.x);
    ob[4]  = f2tf(v.y);
    ob[8]  = f2tf(v.z);
    ob[12] = f2tf(v.w);
}

// ---------------------------------------------------------------------------
// TF32 NT GEMM, 3-stage cp.async pipeline (R15 core, epilogue extended):
// mode 0: write tf32 bits into flash-ready QKV layout selected by z
// mode 1: row-major float [M,1024]
// ---------------------------------------------------------------------------
struct GArgs { const float* A[3]; const unsigned* W[3]; float* C[3]; int mode; };

#define GBK  32
#define GSTR 36
#define G_A_W  (128 * GSTR)                          // 4608 words
#define G_B_W  4096
#define G_STAGE_W (G_A_W + G_B_W)                    // 8704 words per stage
#define G_SMEM_BYTES (3 * G_STAGE_W * 4)             // 104448 B

__global__ __launch_bounds__(256, 2) void gemm_cp(GArgs args)
{
    extern __shared__ float gsm[];
    const uint32_t sb = smem_u32(gsm);
    const int tid  = threadIdx.x;
    const int lane = tid & 31, warp = tid >> 5;
    const int z  = blockIdx.z;
    const float*    __restrict__ A = args.A[z];
    const unsigned* __restrict__ W = args.W[z];
    float* __restrict__ C = args.C[z];
    const int mode = args.mode;
    const int bm = blockIdx.y * 128, bn = blockIdx.x * 128;
    const int wm = (warp >> 1) * 32, wn = (warp & 1) * 64;
    const int g = lane >> 2, t = lane & 3;

    int ar[4], ac[4];
#pragma unroll
    for (int i = 0; i < 4; i++) {
        int idx = tid + i * 256;
        ar[i] = idx >> 3;
        ac[i] = (idx & 7) << 2;
    }
    const int b_kcl   = (tid >> 5) & 3;
    const int b_inner = tid & 31;
    const int b_phi   = tid >> 7;

#define G_ISSUE(ktile, stg) do {                                               \
    uint32_t base_ = sb + (uint32_t)(stg) * (G_STAGE_W * 4);                   \
    const float* As_ = A + (size_t)bm * DD + (ktile) * GBK;                    \
    _Pragma("unroll")                                                          \
    for (int i_ = 0; i_ < 4; i_++)                                             \
        cpa16(base_ + (uint32_t)((ar[i_] * GSTR + ac[i_]) * 4),                \
              As_ + (size_t)ar[i_] * DD + ac[i_]);                             \
    _Pragma("unroll")                                                          \
    for (int i_ = 0; i_ < 4; i_++) {                                           \
        int pl_ = b_phi + 2 * i_;                                              \
        int sidx_ = (pl_ * 4 + b_kcl) * 32 + b_inner;                          \
        const unsigned* Wg_ = W + ((size_t)((bn >> 4) + pl_) * 128             \
                                   + (ktile) * 4 + b_kcl) * 128 + b_inner * 4; \
        cpa16(base_ + (uint32_t)((G_A_W + sidx_ * 4) * 4), Wg_);               \
    }                                                                          \
    CPA_COMMIT();                                                              \
} while (0)

    float acc[2][8][4];
#pragma unroll
    for (int mi = 0; mi < 2; mi++)
#pragma unroll
        for (int nj = 0; nj < 8; nj++)
#pragma unroll
            for (int r = 0; r < 4; r++) acc[mi][nj][r] = 0.0f;

    G_ISSUE(0, 0);
    G_ISSUE(1, 1);

    const int mb0 = wn >> 4;
    const int bfo = 16 * g + 4 * t;

    const int NT = DD / GBK;   // 32
    for (int kt = 0; kt < NT; kt++) {
        if (kt < NT - 1) { CPA_WAIT1(); } else { CPA_WAIT0(); }
        __syncthreads();
        if (kt + 2 < NT) G_ISSUE(kt + 2, (kt + 2) % 3);

        const float*    Ast = gsm + (kt % 3) * G_STAGE_W;
        const unsigned* Bst = (const unsigned*)(Ast + G_A_W);
#pragma unroll
        for (int ks = 0; ks < GBK; ks += 8) {
            const int kcl = ks >> 3;
            unsigned a[2][4];
#pragma unroll
            for (int mi = 0; mi < 2; mi++) {
                int r0 = (wm + mi * 16 + g) * GSTR;
                int r8 = (wm + mi * 16 + g + 8) * GSTR;
                a[mi][0] = f2tf(Ast[r0 + ks + t]);
                a[mi][1] = f2tf(Ast[r8 + ks + t]);
                a[mi][2] = f2tf(Ast[r0 + ks + t + 4]);
                a[mi][3] = f2tf(Ast[r8 + ks + t + 4]);
            }
            uint4 bq[4];
#pragma unroll
            for (int p2 = 0; p2 < 4; p2++)
                bq[p2] = *(const uint4*)(Bst + ((mb0 + p2) * 4 + kcl) * 128 + bfo);
#pragma unroll
            for (int mi = 0; mi < 2; mi++)
#pragma unroll
                for (int p2 = 0; p2 < 4; p2++) {
                    unsigned b0[2] = { bq[p2].x, bq[p2].y };
                    mma8(acc[mi][2 * p2], a[mi], b0);
                    unsigned b1[2] = { bq[p2].z, bq[p2].w };
                    mma8(acc[mi][2 * p2 + 1], a[mi], b1);
                }
        }
    }
#undef G_ISSUE

    if (mode == 0) {
        // Write tf32 bits in the flash-ready layout for this z (Q/K/V)
        unsigned* Cq = (unsigned*)C;
#pragma unroll
        for (int mi = 0; mi < 2; mi++)
#pragma unroll
            for (int rr = 0; rr < 2; rr++) {
                int m  = bm + wm + mi * 16 + g + rr * 8;
                int b_ = m >> 11;
                int s_ = m & (SS - 1);
#pragma unroll
                for (int nj = 0; nj < 8; nj++) {
                    int n  = bn + wn + nj * 8 + 2 * t;
                    int h_ = n >> 6;
                    int dh = n & 63;
                    int head = b_ * HH + h_;
                    Cq[qkv_addr(z, head, s_, dh)]     = f2tf(acc[mi][nj][rr * 2]);
                    Cq[qkv_addr(z, head, s_, dh + 1)] = f2tf(acc[mi][nj][rr * 2 + 1]);
                }
            }
    } else {
#pragma unroll
        for (int mi = 0; mi < 2; mi++)
#pragma unroll
            for (int rr = 0; rr < 2; rr++) {
                int m = bm + wm + mi * 16 + g + rr * 8;
#pragma unroll
                for (int nj = 0; nj < 8; nj++) {
                    int n = bn + wn + nj * 8 + 2 * t;
                    float2 v = make_float2(acc[mi][nj][rr * 2], acc[mi][nj][rr * 2 + 1]);
                    *(float2*)&C[(size_t)m * DD + n] = v;
                }
            }
    }
}

// ---------------------------------------------------------------------------
// TF32 flash attention v4: Q/K/V arrive as tf32 bits in quad/pair layouts.
// All staging is raw 16B copies; all QK fragments are LDS.128, PV B LDS.64.
// smem words: Q 8192 | K 4096 | V 4352 (q-stride 68) | Ps 8704  -> 101376 B
// ---------------------------------------------------------------------------
#define FQ_W 0
#define FK_W 8192
#define FV_W (8192 + 4096)
#define FP_W (8192 + 4096 + 4352)
#define FSTR 68
#define FA_SMEM_BYTES ((8192 + 4096 + 4352 + 8704) * 4)   // 101376 B

__global__ __launch_bounds__(256) void flash_tf32(const unsigned* __restrict__ Q,
                                                  const unsigned* __restrict__ K,
                                                  const unsigned* __restrict__ V,
                                                  const int* __restrict__ vlens,
                                                  float* __restrict__ O)
{
    extern __shared__ unsigned sm[];
    unsigned* Qsm = sm + FQ_W;
    unsigned* Ksm = sm + FK_W;
    unsigned* Vsm = sm + FV_W;
    unsigned (*Ps)[FSTR] = (unsigned (*)[FSTR])(sm + FP_W);

    const int tid  = threadIdx.x;
    const int lane = tid & 31, warp = tid >> 5;
    const int b = blockIdx.x, h = blockIdx.y, qt = blockIdx.z;
    const int head = b * HH + h;

    const unsigned* Qg = Q + (size_t)head * 131072 + qt * 8192;
    const unsigned* Kg = K + (size_t)head * 131072;
    const unsigned* Vg = V + (size_t)head * 131072;
    const int   vlen = vlens[b];
    const int   g = lane >> 2, t = lane & 3;
    const int   wrow = warp * 16;
    const float scale = 0.125f;

    // Q tile: raw linear copy (already quad layout + tf32)
#pragma unroll
    for (int it = 0; it < 8; it++) {
        int u = tid + it * 256;
        *(uint4*)&Qsm[4 * u] = *(const uint4*)(Qg + 4 * u);
    }

    float o[8][4];
#pragma unroll
    for (int nj = 0; nj < 8; nj++)
#pragma unroll
        for (int r = 0; r < 4; r++) o[nj][r] = 0.0f;
    float m0 = -1e30f, m1 = -1e30f, l0 = 0.0f, l1 = 0.0f;

    const int nb = (vlen == 0) ? (SS / 64) : ((vlen + 63) >> 6);

    for (int kbi = 0; kbi < nb; kbi++) {
        const int kb = kbi * 64;
        __syncthreads();
        // K block: raw linear copy (quad layout)
#pragma unroll
        for (int it = 0; it < 4; it++) {
            int u = tid + it * 256;
            *(uint4*)&Ksm[4 * u] = *(const uint4*)(Kg + kbi * 4096 + 4 * u);
        }
        // V block: copy with q-stride 68 (global stride 64 -> smem 68)
#pragma unroll
        for (int it = 0; it < 4; it++) {
            int u = tid + it * 256;
            int q = u >> 5;
            *(uint4*)&Vsm[q * 136 + (u & 31) * 4] = *(const uint4*)(Vg + kbi * 4096 + 4 * u);
        }
        __syncthreads();

        // S = Q @ K^T  (A and B frags all LDS.128)
        float s[8][4];
#pragma unroll
        for (int nj = 0; nj < 8; nj++)
#pragma unroll
            for (int r = 0; r < 4; r++) s[nj][r] = 0.0f;

#pragma unroll
        for (int kc = 0; kc < 8; kc++) {
            uint4 aq = *(const uint4*)&Qsm[(((warp * 8 + kc) * 32) + g * 4 + t) * 4];
            unsigned a[4] = { aq.x, aq.z, aq.y, aq.w };
#pragma unroll
            for (int p = 0; p < 4; p++) {
                uint4 kq = *(const uint4*)&Ksm[(((p * 8 + kc) * 32) + g * 4 + t) * 4];
                unsigned b0[2] = { kq.x, kq.y };
                mma8(s[2 * p], a, b0);
                unsigned b1[2] = { kq.z, kq.w };
                mma8(s[2 * p + 1], a, b1);
            }
        }

        // scale + mask (reference semantics: masked -> -1e6, unscaled)
        float rmax0 = -1e30f, rmax1 = -1e30f;
#pragma unroll
        for (int nj = 0; nj < 8; nj++) {
            int c0 = kb + nj * 8 + 2 * t;
            bool v0 = c0 < vlen, v1 = (c0 + 1) < vlen;
            s[nj][0] = v0 ? s[nj][0] * scale : MASKV;
            s[nj][1] = v1 ? s[nj][1] * scale : MASKV;
            s[nj][2] = v0 ? s[nj][2] * scale : MASKV;
            s[nj][3] = v1 ? s[nj][3] * scale : MASKV;
            rmax0 = fmaxf(rmax0, fmaxf(s[nj][0], s[nj][1]));
            rmax1 = fmaxf(rmax1, fmaxf(s[nj][2], s[nj][3]));
        }
        rmax0 = fmaxf(rmax0, __shfl_xor_sync(0xffffffffu, rmax0, 1));
        rmax0 = fmaxf(rmax0, __shfl_xor_sync(0xffffffffu, rmax0, 2));
        rmax1 = fmaxf(rmax1, __shfl_xor_sync(0xffffffffu, rmax1, 1));
        rmax1 = fmaxf(rmax1, __shfl_xor_sync(0xffffffffu, rmax1, 2));

        float mn0 = fmaxf(m0, rmax0), mn1 = fmaxf(m1, rmax1);
        float corr0 = __expf(m0 - mn0), corr1 = __expf(m1 - mn1);
        float rs0 = 0.0f, rs1 = 0.0f;

#pragma unroll
        for (int nj = 0; nj < 8; nj++) {
            float p0 = __expf(s[nj][0] - mn0);
            float p1 = __expf(s[nj][1] - mn0);
            float p2 = __expf(s[nj][2] - mn1);
            float p3 = __expf(s[nj][3] - mn1);
            rs0 += p0 + p1;
            rs1 += p2 + p3;
            *(uint2*)&Ps[wrow + g][nj * 8 + 2 * t]     = make_uint2(f2tf(p0), f2tf(p1));
            *(uint2*)&Ps[wrow + g + 8][nj * 8 + 2 * t] = make_uint2(f2tf(p2), f2tf(p3));
        }
        rs0 += __shfl_xor_sync(0xffffffffu, rs0, 1);
        rs0 += __shfl_xor_sync(0xffffffffu, rs0, 2);
        rs1 += __shfl_xor_sync(0xffffffffu, rs1, 1);
        rs1 += __shfl_xor_sync(0xffffffffu, rs1, 2);

        l0 = l0 * corr0 + rs0;
        l1 = l1 * corr1 + rs1;
        m0 = mn0; m1 = mn1;
#pragma unroll
        for (int nj = 0; nj < 8; nj++) {
            o[nj][0] *= corr0; o[nj][1] *= corr0;
            o[nj][2] *= corr1; o[nj][3] *= corr1;
        }

        __syncwarp();

        // O += P @ V  (V B-frags: LDS.64 from pair layout, q-stride 68)
#pragma unroll
        for (int ks = 0; ks < 64; ks += 8) {
            unsigned a[4];
            a[0] = Ps[wrow + g][ks + t];
            a[1] = Ps[wrow + g + 8][ks + t];
            a[2] = Ps[wrow + g][ks + t + 4];
            a[3] = Ps[wrow + g + 8][ks + t + 4];
            const int q = (ks >> 1) + t;
#pragma unroll
            for (int nj = 0; nj < 8; nj++) {
                uint2 bv = *(uint2*)(Vsm + (q * FSTR + nj * 8 + g) * 2);
                unsigned bf[2] = { bv.x, bv.y };
                mma8(o[nj], a, bf);
            }
        }
    }

    // Normalize, write concat-head [B,S,D]
    float inv0 = 1.0f / l0, inv1 = 1.0f / l1;
    int row0 = qt * 128 + wrow + g;
    size_t base0 = ((size_t)b * SS + row0) * DD + h * DHH;
    size_t base1 = base0 + (size_t)8 * DD;
#pragma unroll
    for (int nj = 0; nj < 8; nj++) {
        *(float2*)&O[base0 + nj * 8 + 2 * t] = make_float2(o[nj][0] * inv0, o[nj][1] * inv0);
        *(float2*)&O[base1 + nj * 8 + 2 * t] = make_float2(o[nj][2] * inv1, o[nj][3] * inv1);
    }
}

// ---------------------------------------------------------------------------
// Launch. Inputs (metadata order): key, query, value, valid_lens, Wk, Wq, Wv, Wo
// ---------------------------------------------------------------------------
extern "C" void kernel_launch(void* const* d_in, const int* in_sizes, int n_in,
                              void* d_out, int out_size)
{
    const float* key_   = (const float*)d_in[0];
    const float* query_ = (const float*)d_in[1];
    const float* value_ = (const float*)d_in[2];
    const int*   vlens  = (const int*)  d_in[3];
    const float* Wk     = (const float*)d_in[4];
    const float* Wq     = (const float*)d_in[5];
    const float* Wv     = (const float*)d_in[6];
    const float* Wo     = (const float*)d_in[7];
    float* out = (float*)d_out;

    unsigned *qh, *kh, *vh, *wt;
    float *oc;
    cudaGetSymbolAddress((void**)&qh, g_Qh);
    cudaGetSymbolAddress((void**)&kh, g_Kh);
    cudaGetSymbolAddress((void**)&vh, g_Vh);
    cudaGetSymbolAddress((void**)&oc, g_Oc);
    cudaGetSymbolAddress((void**)&wt, g_Wt);

    cudaFuncSetAttribute(gemm_cp, cudaFuncAttributeMaxDynamicSharedMemorySize,
                         G_SMEM_BYTES);
    cudaFuncSetAttribute(flash_tf32, cudaFuncAttributeMaxDynamicSharedMemorySize,
                         FA_SMEM_BYTES);

    // Pre-convert weights to quad-layout tf32 bits: order [Wq, Wk, Wv, Wo]
    CArgs ca;
    ca.W[0] = Wq; ca.W[1] = Wk; ca.W[2] = Wv; ca.W[3] = Wo;
    cvt_w<<<dim3(1024, 4), 256>>>(ca, wt);

    // Fused Q/K/V projections; epilogue writes flash-ready tf32 layouts
    GArgs pa;
    pa.A[0] = query_;  pa.A[1] = key_;                 pa.A[2] = value_;
    pa.W[0] = wt;      pa.W[1] = wt + (size_t)DD * DD; pa.W[2] = wt + (size_t)2 * DD * DD;
    pa.C[0] = (float*)qh; pa.C[1] = (float*)kh;        pa.C[2] = (float*)vh;
    pa.mode = 0;
    gemm_cp<<<dim3(DD / 128, MM / 128, 3), 256, G_SMEM_BYTES>>>(pa);

    // b on blockIdx.x so different-vlen CTAs interleave within each wave
    dim3 ga(BB, HH, SS / 128);    // (4, 16, 16)
    flash_tf32<<<ga, 256, FA_SMEM_BYTES>>>(qh, kh, vh, vlens, oc);

    // Output projection (W = Wo quad tf32)
    GArgs po;
    po.A[0] = po.A[1] = po.A[2] = oc;
    po.W[0] = po.W[1] = po.W[2] = wt + (size_t)3 * DD * DD;
    po.C[0] = po.C[1] = po.C[2] = out;
    po.mode = 1;
    gemm_cp<<<dim3(DD / 128, MM / 128, 1), 256, G_SMEM_BYTES>>>(po);
}